// round 1
// baseline (speedup 1.0000x reference)
#include <cuda_runtime.h>
#include <math_constants.h>
#include <math.h>

#define DIMN 2048
#define BB 2
#define SS 2048
#define HH 16
#define HDD 128
#define MTOT (BB*SS)   // 4096

// Scratch (alloc-free rule: __device__ globals)
__device__ float g_q[(size_t)MTOT * DIMN];
__device__ float g_k[(size_t)MTOT * DIMN];
__device__ float g_v[(size_t)MTOT * DIMN];
__device__ float g_att[(size_t)MTOT * DIMN];

// ---------------------------------------------------------------------------
// SGEMM: C[M,N] = A[M,K] @ B[K,N], all row-major, M=4096, N=K=2048.
// 128x128 block tile, BK=8, 256 threads, 8x8 per thread (split 4+4).
// ---------------------------------------------------------------------------
__global__ __launch_bounds__(256)
void sgemm_kernel(const float* __restrict__ A, const float* __restrict__ Bw,
                  float* __restrict__ C) {
    __shared__ float As[8][132];   // transposed A tile, padded
    __shared__ float Bs[8][128];

    const int t  = threadIdx.x;
    const int bm = blockIdx.y << 7;
    const int bn = blockIdx.x << 7;
    const int tm = t >> 4;         // 0..15
    const int tn = t & 15;         // 0..15

    // A-tile load mapping: row = t>>1 (0..127), k-quad = (t&1)*4
    const int a_row = t >> 1;
    const int a_kq  = (t & 1) << 2;
    // B-tile load mapping: k-row = t>>5 (0..7), col quad = (t&31)*4
    const int b_kr = t >> 5;
    const int b_n4 = (t & 31) << 2;

    float cr[8][8];
    #pragma unroll
    for (int i = 0; i < 8; i++)
        #pragma unroll
        for (int j = 0; j < 8; j++) cr[i][j] = 0.f;

    for (int k0 = 0; k0 < DIMN; k0 += 8) {
        __syncthreads();
        // load A tile (transposed into As)
        float4 av = *(const float4*)(A + (size_t)(bm + a_row) * DIMN + k0 + a_kq);
        As[a_kq + 0][a_row] = av.x;
        As[a_kq + 1][a_row] = av.y;
        As[a_kq + 2][a_row] = av.z;
        As[a_kq + 3][a_row] = av.w;
        // load B tile
        *(float4*)&Bs[b_kr][b_n4] =
            *(const float4*)(Bw + (size_t)(k0 + b_kr) * DIMN + bn + b_n4);
        __syncthreads();

        #pragma unroll
        for (int kk = 0; kk < 8; kk++) {
            float a[8], b[8];
            *(float4*)&a[0] = *(float4*)&As[kk][tm * 4];
            *(float4*)&a[4] = *(float4*)&As[kk][64 + tm * 4];
            *(float4*)&b[0] = *(float4*)&Bs[kk][tn * 4];
            *(float4*)&b[4] = *(float4*)&Bs[kk][64 + tn * 4];
            #pragma unroll
            for (int i = 0; i < 8; i++)
                #pragma unroll
                for (int j = 0; j < 8; j++)
                    cr[i][j] += a[i] * b[j];
        }
    }

    #pragma unroll
    for (int i = 0; i < 8; i++) {
        int m = bm + tm * 4 + (i & 3) + ((i >> 2) << 6);
        float* cp = C + (size_t)m * DIMN + bn + tn * 4;
        *(float4*)cp        = make_float4(cr[i][0], cr[i][1], cr[i][2], cr[i][3]);
        *(float4*)(cp + 64) = make_float4(cr[i][4], cr[i][5], cr[i][6], cr[i][7]);
    }
}

// ---------------------------------------------------------------------------
// RoPE on q and k, layout [B*S, DIM]. Adjacent-pair rotation, angle = s*inv_freq.
// ---------------------------------------------------------------------------
__global__ void rope_kernel(float* __restrict__ q, float* __restrict__ k) {
    int idx = blockIdx.x * blockDim.x + threadIdx.x;   // pair index
    int pair = idx & (DIMN / 2 - 1);                   // 0..1023
    int row  = idx >> 10;                              // 0..4095
    int s    = row & (SS - 1);
    int dp   = pair & (HDD / 2 - 1);                   // 0..63

    float inv = powf(10000.0f, -(float)dp * (1.0f / 64.0f));
    float ang = (float)s * inv;
    float sn, cs;
    sincosf(ang, &sn, &cs);

    size_t base = (size_t)row * DIMN + 2 * pair;
    float2 qe = *(float2*)(q + base);
    *(float2*)(q + base) = make_float2(qe.x * cs - qe.y * sn, qe.x * sn + qe.y * cs);
    float2 ke = *(float2*)(k + base);
    *(float2*)(k + base) = make_float2(ke.x * cs - ke.y * sn, ke.x * sn + ke.y * cs);
}

// ---------------------------------------------------------------------------
// Flash attention, causal, BM=BN=64, HD=128, 256 threads.
// Phase A: S=QK^T (16x16 thread grid, 4x4 each). Phase B: online softmax
// (4 threads/row, quad shuffles). Phase C: acc += P@V (interleaved cols).
// ---------------------------------------------------------------------------
#define FLASH_SMEM ((64*129*2 + 64*128 + 64*65) * 4)

__global__ __launch_bounds__(256, 1)
void flash_kernel(const float* __restrict__ Q, const float* __restrict__ K,
                  const float* __restrict__ V, float* __restrict__ O) {
    extern __shared__ float sm[];
    float* Qs = sm;                    // [64][129]
    float* Ks = sm + 64 * 129;         // [64][129]
    float* Vs = Ks + 64 * 129;         // [64][128]
    float* Ss = Vs + 64 * 128;         // [64][65]

    const int t  = threadIdx.x;
    const int qt = blockIdx.x, h = blockIdx.y, b = blockIdx.z;
    const int q0 = qt * 64;
    const float scale = 0.08838834764831845f;   // 1/sqrt(128)

    const float* Qp = Q + ((size_t)b * SS) * DIMN + h * HDD;
    const float* Kp = K + ((size_t)b * SS) * DIMN + h * HDD;
    const float* Vp = V + ((size_t)b * SS) * DIMN + h * HDD;

    // load Q tile once
    for (int i = t; i < 64 * 32; i += 256) {
        int r = i >> 5, c = (i & 31) << 2;
        float4 v4 = *(const float4*)(Qp + (size_t)(q0 + r) * DIMN + c);
        float* dst = Qs + r * 129 + c;
        dst[0] = v4.x; dst[1] = v4.y; dst[2] = v4.z; dst[3] = v4.w;
    }

    const int tmq = t >> 4, tnq = t & 15;
    const int i0 = tmq * 4, j0 = tnq * 4;
    const int r = t >> 2, q4 = t & 3;

    float4 acc[8];
    #pragma unroll
    for (int jj = 0; jj < 8; jj++) acc[jj] = make_float4(0.f, 0.f, 0.f, 0.f);
    float mval = -CUDART_INF_F, lval = 0.f;

    for (int kt = 0; kt <= qt; kt++) {
        const int k0 = kt * 64;
        __syncthreads();   // prior-iter readers of Ks/Vs/Ss done
        for (int i = t; i < 64 * 32; i += 256) {
            int rr = i >> 5, c = (i & 31) << 2;
            float4 kv = *(const float4*)(Kp + (size_t)(k0 + rr) * DIMN + c);
            float* kd = Ks + rr * 129 + c;
            kd[0] = kv.x; kd[1] = kv.y; kd[2] = kv.z; kd[3] = kv.w;
            *(float4*)(Vs + rr * 128 + c) =
                *(const float4*)(Vp + (size_t)(k0 + rr) * DIMN + c);
        }
        __syncthreads();

        // ---- Phase A: scores tile ----
        float cacc[4][4];
        #pragma unroll
        for (int x = 0; x < 4; x++)
            #pragma unroll
            for (int y = 0; y < 4; y++) cacc[x][y] = 0.f;
        #pragma unroll 4
        for (int d = 0; d < 128; d++) {
            float qr[4], kr[4];
            #pragma unroll
            for (int x = 0; x < 4; x++) qr[x] = Qs[(i0 + x) * 129 + d];
            #pragma unroll
            for (int y = 0; y < 4; y++) kr[y] = Ks[(j0 + y) * 129 + d];
            #pragma unroll
            for (int x = 0; x < 4; x++)
                #pragma unroll
                for (int y = 0; y < 4; y++) cacc[x][y] += qr[x] * kr[y];
        }
        #pragma unroll
        for (int x = 0; x < 4; x++) {
            int gi = q0 + i0 + x;
            #pragma unroll
            for (int y = 0; y < 4; y++) {
                int gj = k0 + j0 + y;
                float sv = cacc[x][y] * scale;
                if (gj > gi) sv = -CUDART_INF_F;
                Ss[(i0 + x) * 65 + j0 + y] = sv;
            }
        }
        __syncthreads();

        // ---- Phase B: online softmax (quad = 4 threads per row) ----
        float* srow = Ss + r * 65;
        float mloc = -CUDART_INF_F;
        #pragma unroll
        for (int j = 0; j < 16; j++) mloc = fmaxf(mloc, srow[q4 * 16 + j]);
        mloc = fmaxf(mloc, __shfl_xor_sync(0xFFFFFFFFu, mloc, 1));
        mloc = fmaxf(mloc, __shfl_xor_sync(0xFFFFFFFFu, mloc, 2));
        float mnew = fmaxf(mval, mloc);
        float corr = __expf(mval - mnew);
        float lloc = 0.f;
        #pragma unroll
        for (int j = 0; j < 16; j++) {
            float p = __expf(srow[q4 * 16 + j] - mnew);
            srow[q4 * 16 + j] = p;
            lloc += p;
        }
        lloc += __shfl_xor_sync(0xFFFFFFFFu, lloc, 1);
        lloc += __shfl_xor_sync(0xFFFFFFFFu, lloc, 2);
        lval = lval * corr + lloc;
        mval = mnew;
        #pragma unroll
        for (int jj = 0; jj < 8; jj++) {
            acc[jj].x *= corr; acc[jj].y *= corr;
            acc[jj].z *= corr; acc[jj].w *= corr;
        }
        __syncwarp();   // quad's P writes visible before full-row reads

        // ---- Phase C: acc += P @ V (cols: 16*jj + 4*q4 + e, conflict-free) ----
        for (int kk = 0; kk < 64; kk++) {
            float p = srow[kk];
            const float* vr = Vs + kk * 128 + q4 * 4;
            #pragma unroll
            for (int jj = 0; jj < 8; jj++) {
                float4 vv = *(const float4*)(vr + jj * 16);
                acc[jj].x += p * vv.x; acc[jj].y += p * vv.y;
                acc[jj].z += p * vv.z; acc[jj].w += p * vv.w;
            }
        }
    }

    float invl = 1.f / lval;
    float* orow = O + ((size_t)b * SS + q0 + r) * DIMN + h * HDD + q4 * 4;
    #pragma unroll
    for (int jj = 0; jj < 8; jj++) {
        float4 w = acc[jj];
        w.x *= invl; w.y *= invl; w.z *= invl; w.w *= invl;
        *(float4*)(orow + jj * 16) = w;
    }
}

// ---------------------------------------------------------------------------
extern "C" void kernel_launch(void* const* d_in, const int* in_sizes, int n_in,
                              void* d_out, int out_size) {
    const float* x  = (const float*)d_in[0];
    const float* Wq = (const float*)d_in[1];
    const float* Wk = (const float*)d_in[2];
    const float* Wv = (const float*)d_in[3];
    const float* Wo = (const float*)d_in[4];
    float* out = (float*)d_out;

    float *q, *k, *v, *att;
    cudaGetSymbolAddress((void**)&q, g_q);
    cudaGetSymbolAddress((void**)&k, g_k);
    cudaGetSymbolAddress((void**)&v, g_v);
    cudaGetSymbolAddress((void**)&att, g_att);

    dim3 gg(DIMN / 128, MTOT / 128);   // (16, 32)
    sgemm_kernel<<<gg, 256>>>(x, Wq, q);
    sgemm_kernel<<<gg, 256>>>(x, Wk, k);
    sgemm_kernel<<<gg, 256>>>(x, Wv, v);

    int rope_blocks = (MTOT * (DIMN / 2)) / 256;       // 16384
    rope_kernel<<<rope_blocks, 256>>>(q, k);

    cudaFuncSetAttribute(flash_kernel,
                         cudaFuncAttributeMaxDynamicSharedMemorySize, FLASH_SMEM);
    flash_kernel<<<dim3(SS / 64, HH, BB), 256, FLASH_SMEM>>>(q, k, v, att);

    sgemm_kernel<<<gg, 256>>>(att, Wo, out);
}

// round 2
// speedup vs baseline: 1.0403x; 1.0403x over previous
#include <cuda_runtime.h>
#include <math_constants.h>
#include <math.h>

#define DIMN 2048
#define BB 2
#define SS 2048
#define HH 16
#define HDD 128
#define MTOT (BB*SS)   // 4096

// Scratch (alloc-free rule: __device__ globals)
__device__ float g_q[(size_t)MTOT * DIMN];
__device__ float g_k[(size_t)MTOT * DIMN];
__device__ float g_v[(size_t)MTOT * DIMN];
__device__ float g_att[(size_t)MTOT * DIMN];

// ---------------------------------------------------------------------------
// Helpers: tf32 mma path
// ---------------------------------------------------------------------------
__device__ __forceinline__ unsigned cvt_tf32(float x) {
    unsigned r;
    asm("cvt.rna.tf32.f32 %0, %1;" : "=r"(r) : "f"(x));
    return r;
}

__device__ __forceinline__ void mma_tf32(float* d, const unsigned* a, const unsigned* b) {
    asm volatile(
        "mma.sync.aligned.m16n8k8.row.col.f32.tf32.tf32.f32 "
        "{%0,%1,%2,%3}, {%4,%5,%6,%7}, {%8,%9}, {%0,%1,%2,%3};"
        : "+f"(d[0]), "+f"(d[1]), "+f"(d[2]), "+f"(d[3])
        : "r"(a[0]), "r"(a[1]), "r"(a[2]), "r"(a[3]), "r"(b[0]), "r"(b[1]));
}

__device__ __forceinline__ void cp_async16(void* smem, const void* gmem) {
    unsigned s = (unsigned)__cvta_generic_to_shared(smem);
    asm volatile("cp.async.cg.shared.global [%0], [%1], 16;\n" :: "r"(s), "l"(gmem));
}

// ---------------------------------------------------------------------------
// Tensor-core GEMM (3xtf32, fp32-class accuracy):
// C[M,N] = A[M,K] @ B[K,N], row-major, M=4096, N=K=2048.
// 128x128x16 tile, 256 threads, warp grid 2x4 (64x32 per warp),
// cp.async double-buffered. mma.m16n8k8.tf32.
// ---------------------------------------------------------------------------
__global__ __launch_bounds__(256)
void tgemm_kernel(const float* __restrict__ A, const float* __restrict__ Bw,
                  float* __restrict__ C) {
    __shared__ float As[2][128][20];    // [m][k], stride 20: frag reads conflict-free
    __shared__ float Bs[2][16][136];    // [k][n], stride 136: frag reads conflict-free

    const int t    = threadIdx.x;
    const int bm   = blockIdx.y << 7;
    const int bn   = blockIdx.x << 7;
    const int lane = t & 31;
    const int warp = t >> 5;
    const int wm   = warp >> 2;          // 0..1  -> m offset 64*wm
    const int wn   = warp & 3;           // 0..3  -> n offset 32*wn
    const int gr   = lane >> 2;          // 0..7
    const int tg   = lane & 3;           // 0..3

    float acc[4][4][4];
    #pragma unroll
    for (int mi = 0; mi < 4; mi++)
        #pragma unroll
        for (int ni = 0; ni < 4; ni++)
            #pragma unroll
            for (int e = 0; e < 4; e++) acc[mi][ni][e] = 0.f;

    // tile load: A 128x16 (512 x 16B chunks), B 16x128 (512 chunks); 2 each/thread
    const int a_row = t >> 1;                 // chunk c=t+256i: row=c>>2 … recompute below
    (void)a_row;

    #define LOAD_TILE(buf, k0)                                                   \
        do {                                                                     \
            _Pragma("unroll")                                                    \
            for (int i = 0; i < 2; i++) {                                        \
                int c = t + 256 * i;                                             \
                int row = c >> 2, q = (c & 3) << 2;                              \
                cp_async16(&As[buf][row][q],                                     \
                           A + (size_t)(bm + row) * DIMN + (k0) + q);            \
            }                                                                    \
            _Pragma("unroll")                                                    \
            for (int i = 0; i < 2; i++) {                                        \
                int c = t + 256 * i;                                             \
                int row = c >> 5, cq = (c & 31) << 2;                            \
                cp_async16(&Bs[buf][row][cq],                                    \
                           Bw + (size_t)((k0) + row) * DIMN + bn + cq);          \
            }                                                                    \
        } while (0)

    LOAD_TILE(0, 0);
    asm volatile("cp.async.commit_group;\n");

    const int NT = DIMN / 16;   // 128
    for (int kt = 0; kt < NT; kt++) {
        const int buf = kt & 1;
        if (kt + 1 < NT) {
            LOAD_TILE(buf ^ 1, (kt + 1) * 16);
            asm volatile("cp.async.commit_group;\n");
            asm volatile("cp.async.wait_group 1;\n");
        } else {
            asm volatile("cp.async.wait_group 0;\n");
        }
        __syncthreads();

        #pragma unroll
        for (int ks = 0; ks < 2; ks++) {
            const int k = ks * 8;
            unsigned Ah[4][4], Al[4][4];
            #pragma unroll
            for (int mi = 0; mi < 4; mi++) {
                const int m0 = wm * 64 + mi * 16;
                float a0 = As[buf][m0 + gr    ][k + tg    ];
                float a1 = As[buf][m0 + gr + 8][k + tg    ];
                float a2 = As[buf][m0 + gr    ][k + tg + 4];
                float a3 = As[buf][m0 + gr + 8][k + tg + 4];
                Ah[mi][0] = cvt_tf32(a0); Al[mi][0] = cvt_tf32(a0 - __uint_as_float(Ah[mi][0]));
                Ah[mi][1] = cvt_tf32(a1); Al[mi][1] = cvt_tf32(a1 - __uint_as_float(Ah[mi][1]));
                Ah[mi][2] = cvt_tf32(a2); Al[mi][2] = cvt_tf32(a2 - __uint_as_float(Ah[mi][2]));
                Ah[mi][3] = cvt_tf32(a3); Al[mi][3] = cvt_tf32(a3 - __uint_as_float(Ah[mi][3]));
            }
            unsigned Bh[4][2], Bl[4][2];
            #pragma unroll
            for (int ni = 0; ni < 4; ni++) {
                const int n0 = wn * 32 + ni * 8;
                float b0 = Bs[buf][k + tg    ][n0 + gr];
                float b1 = Bs[buf][k + tg + 4][n0 + gr];
                Bh[ni][0] = cvt_tf32(b0); Bl[ni][0] = cvt_tf32(b0 - __uint_as_float(Bh[ni][0]));
                Bh[ni][1] = cvt_tf32(b1); Bl[ni][1] = cvt_tf32(b1 - __uint_as_float(Bh[ni][1]));
            }
            #pragma unroll
            for (int mi = 0; mi < 4; mi++)
                #pragma unroll
                for (int ni = 0; ni < 4; ni++) {
                    mma_tf32(acc[mi][ni], Ah[mi], Bh[ni]);
                    mma_tf32(acc[mi][ni], Al[mi], Bh[ni]);
                    mma_tf32(acc[mi][ni], Ah[mi], Bl[ni]);
                }
        }
        __syncthreads();
    }

    // epilogue: c0,c1 at (gr, 2tg), (gr, 2tg+1); c2,c3 at row+8
    #pragma unroll
    for (int mi = 0; mi < 4; mi++) {
        #pragma unroll
        for (int ni = 0; ni < 4; ni++) {
            const int m = bm + wm * 64 + mi * 16 + gr;
            const int n = bn + wn * 32 + ni * 8 + tg * 2;
            *(float2*)(C + (size_t)m * DIMN + n) =
                make_float2(acc[mi][ni][0], acc[mi][ni][1]);
            *(float2*)(C + (size_t)(m + 8) * DIMN + n) =
                make_float2(acc[mi][ni][2], acc[mi][ni][3]);
        }
    }
}

// ---------------------------------------------------------------------------
// RoPE on q and k, layout [B*S, DIM]. Adjacent-pair rotation, angle = s*inv_freq.
// ---------------------------------------------------------------------------
__global__ void rope_kernel(float* __restrict__ q, float* __restrict__ k) {
    int idx = blockIdx.x * blockDim.x + threadIdx.x;   // pair index
    int pair = idx & (DIMN / 2 - 1);                   // 0..1023
    int row  = idx >> 10;                              // 0..4095
    int s    = row & (SS - 1);
    int dp   = pair & (HDD / 2 - 1);                   // 0..63

    float inv = powf(10000.0f, -(float)dp * (1.0f / 64.0f));
    float ang = (float)s * inv;
    float sn, cs;
    sincosf(ang, &sn, &cs);

    size_t base = (size_t)row * DIMN + 2 * pair;
    float2 qe = *(float2*)(q + base);
    *(float2*)(q + base) = make_float2(qe.x * cs - qe.y * sn, qe.x * sn + qe.y * cs);
    float2 ke = *(float2*)(k + base);
    *(float2*)(k + base) = make_float2(ke.x * cs - ke.y * sn, ke.x * sn + ke.y * cs);
}

// ---------------------------------------------------------------------------
// Flash attention, causal, BM=BN=64, HD=128, 256 threads (fp32).
// ---------------------------------------------------------------------------
#define FLASH_SMEM ((64*129*2 + 64*128 + 64*65) * 4)

__global__ __launch_bounds__(256, 1)
void flash_kernel(const float* __restrict__ Q, const float* __restrict__ K,
                  const float* __restrict__ V, float* __restrict__ O) {
    extern __shared__ float sm[];
    float* Qs = sm;                    // [64][129]
    float* Ks = sm + 64 * 129;         // [64][129]
    float* Vs = Ks + 64 * 129;         // [64][128]
    float* Ss = Vs + 64 * 128;         // [64][65]

    const int t  = threadIdx.x;
    const int qt = blockIdx.x, h = blockIdx.y, b = blockIdx.z;
    const int q0 = qt * 64;
    const float scale = 0.08838834764831845f;   // 1/sqrt(128)

    const float* Qp = Q + ((size_t)b * SS) * DIMN + h * HDD;
    const float* Kp = K + ((size_t)b * SS) * DIMN + h * HDD;
    const float* Vp = V + ((size_t)b * SS) * DIMN + h * HDD;

    for (int i = t; i < 64 * 32; i += 256) {
        int r = i >> 5, c = (i & 31) << 2;
        float4 v4 = *(const float4*)(Qp + (size_t)(q0 + r) * DIMN + c);
        float* dst = Qs + r * 129 + c;
        dst[0] = v4.x; dst[1] = v4.y; dst[2] = v4.z; dst[3] = v4.w;
    }

    const int tmq = t >> 4, tnq = t & 15;
    const int i0 = tmq * 4, j0 = tnq * 4;
    const int r = t >> 2, q4 = t & 3;

    float4 acc[8];
    #pragma unroll
    for (int jj = 0; jj < 8; jj++) acc[jj] = make_float4(0.f, 0.f, 0.f, 0.f);
    float mval = -CUDART_INF_F, lval = 0.f;

    for (int kt = 0; kt <= qt; kt++) {
        const int k0 = kt * 64;
        __syncthreads();
        for (int i = t; i < 64 * 32; i += 256) {
            int rr = i >> 5, c = (i & 31) << 2;
            float4 kv = *(const float4*)(Kp + (size_t)(k0 + rr) * DIMN + c);
            float* kd = Ks + rr * 129 + c;
            kd[0] = kv.x; kd[1] = kv.y; kd[2] = kv.z; kd[3] = kv.w;
            *(float4*)(Vs + rr * 128 + c) =
                *(const float4*)(Vp + (size_t)(k0 + rr) * DIMN + c);
        }
        __syncthreads();

        float cacc[4][4];
        #pragma unroll
        for (int x = 0; x < 4; x++)
            #pragma unroll
            for (int y = 0; y < 4; y++) cacc[x][y] = 0.f;
        #pragma unroll 4
        for (int d = 0; d < 128; d++) {
            float qr[4], kr[4];
            #pragma unroll
            for (int x = 0; x < 4; x++) qr[x] = Qs[(i0 + x) * 129 + d];
            #pragma unroll
            for (int y = 0; y < 4; y++) kr[y] = Ks[(j0 + y) * 129 + d];
            #pragma unroll
            for (int x = 0; x < 4; x++)
                #pragma unroll
                for (int y = 0; y < 4; y++) cacc[x][y] += qr[x] * kr[y];
        }
        #pragma unroll
        for (int x = 0; x < 4; x++) {
            int gi = q0 + i0 + x;
            #pragma unroll
            for (int y = 0; y < 4; y++) {
                int gj = k0 + j0 + y;
                float sv = cacc[x][y] * scale;
                if (gj > gi) sv = -CUDART_INF_F;
                Ss[(i0 + x) * 65 + j0 + y] = sv;
            }
        }
        __syncthreads();

        float* srow = Ss + r * 65;
        float mloc = -CUDART_INF_F;
        #pragma unroll
        for (int j = 0; j < 16; j++) mloc = fmaxf(mloc, srow[q4 * 16 + j]);
        mloc = fmaxf(mloc, __shfl_xor_sync(0xFFFFFFFFu, mloc, 1));
        mloc = fmaxf(mloc, __shfl_xor_sync(0xFFFFFFFFu, mloc, 2));
        float mnew = fmaxf(mval, mloc);
        float corr = __expf(mval - mnew);
        float lloc = 0.f;
        #pragma unroll
        for (int j = 0; j < 16; j++) {
            float p = __expf(srow[q4 * 16 + j] - mnew);
            srow[q4 * 16 + j] = p;
            lloc += p;
        }
        lloc += __shfl_xor_sync(0xFFFFFFFFu, lloc, 1);
        lloc += __shfl_xor_sync(0xFFFFFFFFu, lloc, 2);
        lval = lval * corr + lloc;
        mval = mnew;
        #pragma unroll
        for (int jj = 0; jj < 8; jj++) {
            acc[jj].x *= corr; acc[jj].y *= corr;
            acc[jj].z *= corr; acc[jj].w *= corr;
        }
        __syncwarp();

        for (int kk = 0; kk < 64; kk++) {
            float p = srow[kk];
            const float* vr = Vs + kk * 128 + q4 * 4;
            #pragma unroll
            for (int jj = 0; jj < 8; jj++) {
                float4 vv = *(const float4*)(vr + jj * 16);
                acc[jj].x += p * vv.x; acc[jj].y += p * vv.y;
                acc[jj].z += p * vv.z; acc[jj].w += p * vv.w;
            }
        }
    }

    float invl = 1.f / lval;
    float* orow = O + ((size_t)b * SS + q0 + r) * DIMN + h * HDD + q4 * 4;
    #pragma unroll
    for (int jj = 0; jj < 8; jj++) {
        float4 w = acc[jj];
        w.x *= invl; w.y *= invl; w.z *= invl; w.w *= invl;
        *(float4*)(orow + jj * 16) = w;
    }
}

// ---------------------------------------------------------------------------
extern "C" void kernel_launch(void* const* d_in, const int* in_sizes, int n_in,
                              void* d_out, int out_size) {
    const float* x  = (const float*)d_in[0];
    const float* Wq = (const float*)d_in[1];
    const float* Wk = (const float*)d_in[2];
    const float* Wv = (const float*)d_in[3];
    const float* Wo = (const float*)d_in[4];
    float* out = (float*)d_out;

    float *q, *k, *v, *att;
    cudaGetSymbolAddress((void**)&q, g_q);
    cudaGetSymbolAddress((void**)&k, g_k);
    cudaGetSymbolAddress((void**)&v, g_v);
    cudaGetSymbolAddress((void**)&att, g_att);

    dim3 gg(DIMN / 128, MTOT / 128);   // (16, 32)
    tgemm_kernel<<<gg, 256>>>(x, Wq, q);
    tgemm_kernel<<<gg, 256>>>(x, Wk, k);
    tgemm_kernel<<<gg, 256>>>(x, Wv, v);

    int rope_blocks = (MTOT * (DIMN / 2)) / 256;       // 16384
    rope_kernel<<<rope_blocks, 256>>>(q, k);

    cudaFuncSetAttribute(flash_kernel,
                         cudaFuncAttributeMaxDynamicSharedMemorySize, FLASH_SMEM);
    flash_kernel<<<dim3(SS / 64, HH, BB), 256, FLASH_SMEM>>>(q, k, v, att);

    tgemm_kernel<<<gg, 256>>>(att, Wo, out);
}

// round 5
// speedup vs baseline: 1.5195x; 1.4607x over previous
#include <cuda_runtime.h>
#include <cuda_bf16.h>
#include <math_constants.h>
#include <math.h>
#include <cstdint>

#define DIMN 2048
#define BB 2
#define SS 2048
#define HH 16
#define HDD 128
#define MTOT (BB*SS)   // 4096

// ---------------------------------------------------------------------------
// Scratch (alloc-free rule: __device__ globals)
// ---------------------------------------------------------------------------
__device__ float g_q[(size_t)MTOT * DIMN];
__device__ float g_k[(size_t)MTOT * DIMN];
__device__ float g_v[(size_t)MTOT * DIMN];
__device__ float g_att[(size_t)MTOT * DIMN];
__device__ __nv_bfloat16 g_xh[(size_t)MTOT * DIMN];
__device__ __nv_bfloat16 g_xl[(size_t)MTOT * DIMN];
__device__ __nv_bfloat16 g_ath[(size_t)MTOT * DIMN];
__device__ __nv_bfloat16 g_atl[(size_t)MTOT * DIMN];
__device__ __nv_bfloat16 g_wth[4][(size_t)DIMN * DIMN];   // W^T hi, [N][K]
__device__ __nv_bfloat16 g_wtl[4][(size_t)DIMN * DIMN];   // W^T lo

// ---------------------------------------------------------------------------
// PTX helpers (generic sm_80+ features only: cp.async, ldmatrix, mma.sync)
// ---------------------------------------------------------------------------
__device__ __forceinline__ void cp_async16_s(uint32_t s, const void* g) {
    asm volatile("cp.async.cg.shared.global [%0], [%1], 16;\n" :: "r"(s), "l"(g));
}
#define CP_COMMIT() asm volatile("cp.async.commit_group;\n")

__device__ __forceinline__ uint32_t smem_u32(const void* p) {
    uint32_t a;
    asm("{ .reg .u64 t; cvta.to.shared.u64 t, %1; cvt.u32.u64 %0, t; }"
        : "=r"(a) : "l"(p));
    return a;
}

__device__ __forceinline__ void ldsm_x4(uint32_t addr, uint32_t* r) {
    asm volatile("ldmatrix.sync.aligned.m8n8.x4.shared.b16 {%0,%1,%2,%3}, [%4];"
                 : "=r"(r[0]), "=r"(r[1]), "=r"(r[2]), "=r"(r[3]) : "r"(addr));
}
__device__ __forceinline__ void ldsm_x2(uint32_t addr, uint32_t* r) {
    asm volatile("ldmatrix.sync.aligned.m8n8.x2.shared.b16 {%0,%1}, [%2];"
                 : "=r"(r[0]), "=r"(r[1]) : "r"(addr));
}

__device__ __forceinline__ void mma_bf16(float* d, const uint32_t* a,
                                         const uint32_t* b) {
    asm volatile(
        "mma.sync.aligned.m16n8k16.row.col.f32.bf16.bf16.f32 "
        "{%0,%1,%2,%3}, {%4,%5,%6,%7}, {%8,%9}, {%0,%1,%2,%3};"
        : "+f"(d[0]), "+f"(d[1]), "+f"(d[2]), "+f"(d[3])
        : "r"(a[0]), "r"(a[1]), "r"(a[2]), "r"(a[3]), "r"(b[0]), "r"(b[1]));
}

// ---------------------------------------------------------------------------
// Prep kernel 1: split fp32 rows into bf16 hi/lo (same layout)
// ---------------------------------------------------------------------------
__global__ void split_rows(const float* __restrict__ in,
                           __nv_bfloat16* __restrict__ h,
                           __nv_bfloat16* __restrict__ l) {
    size_t i = ((size_t)blockIdx.x * 256 + threadIdx.x) * 4;
    float4 v = *(const float4*)(in + i);
    __nv_bfloat16 h0 = __float2bfloat16(v.x), h1 = __float2bfloat16(v.y);
    __nv_bfloat16 h2 = __float2bfloat16(v.z), h3 = __float2bfloat16(v.w);
    __nv_bfloat16 l0 = __float2bfloat16(v.x - __bfloat162float(h0));
    __nv_bfloat16 l1 = __float2bfloat16(v.y - __bfloat162float(h1));
    __nv_bfloat16 l2 = __float2bfloat16(v.z - __bfloat162float(h2));
    __nv_bfloat16 l3 = __float2bfloat16(v.w - __bfloat162float(h3));
    *(__nv_bfloat162*)(h + i)     = __nv_bfloat162(h0, h1);
    *(__nv_bfloat162*)(h + i + 2) = __nv_bfloat162(h2, h3);
    *(__nv_bfloat162*)(l + i)     = __nv_bfloat162(l0, l1);
    *(__nv_bfloat162*)(l + i + 2) = __nv_bfloat162(l2, l3);
}

// ---------------------------------------------------------------------------
// Prep kernel 2: transpose W [K,N] -> W^T [N,K] and split into bf16 hi/lo
// ---------------------------------------------------------------------------
__global__ void split_transpose(const float* __restrict__ W,
                                __nv_bfloat16* __restrict__ th,
                                __nv_bfloat16* __restrict__ tl) {
    __shared__ float ts[32][33];
    const int bx = blockIdx.x * 32, by = blockIdx.y * 32;
    const int tx = threadIdx.x, ty = threadIdx.y;   // 32 x 8
    #pragma unroll
    for (int j = 0; j < 4; j++)
        ts[ty + 8 * j][tx] = W[(size_t)(by + ty + 8 * j) * DIMN + bx + tx];
    __syncthreads();
    #pragma unroll
    for (int j = 0; j < 4; j++) {
        float v = ts[tx][ty + 8 * j];
        __nv_bfloat16 h = __float2bfloat16(v);
        __nv_bfloat16 l = __float2bfloat16(v - __bfloat162float(h));
        size_t o = (size_t)(bx + ty + 8 * j) * DIMN + by + tx;
        th[o] = h;
        tl[o] = l;
    }
}

// ---------------------------------------------------------------------------
// bf16 3-term split GEMM on mma.sync.m16n8k16:
// C[M,N] = A[M,K] @ B^T, B stored [N,K] K-major (W^T), hi/lo precomputed.
// Tile 128x128x32, 256 threads, warp grid 2x4 (warp tile 64x32),
// cp.async double-buffered, ldmatrix fragments, padded 80B rows.
// ---------------------------------------------------------------------------
#define BKT 32
#define ROWB 80                       // bytes per padded smem row (32 bf16 + 8 pad)
#define ASTRIDE (128 * ROWB)          // 10240 B per array
#define STG_BYTES (4 * ASTRIDE)       // Ah, Al, Bh, Bl
#define GSMEM (2 * STG_BYTES)         // 81920 B

__device__ __forceinline__ void fill_stage(uint32_t stg,
        const __nv_bfloat16* ah, const __nv_bfloat16* al,
        const __nv_bfloat16* bh, const __nv_bfloat16* bl,
        int k0, int t) {
    #pragma unroll
    for (int i = 0; i < 2; i++) {
        int c = t + (i << 8);              // 0..511
        int row = c >> 2, cc = c & 3;
        uint32_t so = (uint32_t)(row * ROWB + cc * 16);
        size_t g = (size_t)row * DIMN + k0 + cc * 8;
        cp_async16_s(stg + so,               ah + g);
        cp_async16_s(stg + ASTRIDE + so,     al + g);
        cp_async16_s(stg + 2 * ASTRIDE + so, bh + g);
        cp_async16_s(stg + 3 * ASTRIDE + so, bl + g);
    }
}

__global__ __launch_bounds__(256)
void hgemm3(const __nv_bfloat16* __restrict__ Ah, const __nv_bfloat16* __restrict__ Al,
            const __nv_bfloat16* __restrict__ Bh, const __nv_bfloat16* __restrict__ Bl,
            float* __restrict__ C) {
    extern __shared__ char dsm[];
    const uint32_t base = smem_u32(dsm);

    const int t    = threadIdx.x;
    const int lane = t & 31;
    const int warp = t >> 5;
    const int wm   = warp >> 2;           // 0..1 -> m offset 64*wm
    const int wn   = warp & 3;            // 0..3 -> n offset 32*wn
    const int bm   = blockIdx.y << 7;
    const int bn   = blockIdx.x << 7;

    const __nv_bfloat16* ah0 = Ah + (size_t)bm * DIMN;
    const __nv_bfloat16* al0 = Al + (size_t)bm * DIMN;
    const __nv_bfloat16* bh0 = Bh + (size_t)bn * DIMN;
    const __nv_bfloat16* bl0 = Bl + (size_t)bn * DIMN;

    float acc[4][4][4];
    #pragma unroll
    for (int mi = 0; mi < 4; mi++)
        #pragma unroll
        for (int ni = 0; ni < 4; ni++)
            #pragma unroll
            for (int e = 0; e < 4; e++) acc[mi][ni][e] = 0.f;

    // ldmatrix lane addressing (within one array):
    //   A x4: rows m0 + (lane&15), k-half (lane>>4)
    //   B x2: rows n0 + (lane&7),  k-half (lane>>3)&1
    const uint32_t a_lrow = (uint32_t)(lane & 15);
    const uint32_t a_khalf = (uint32_t)(lane >> 4) * 16;
    const uint32_t b_lrow = (uint32_t)(lane & 7);
    const uint32_t b_khalf = (uint32_t)((lane >> 3) & 1) * 16;

    fill_stage(base, ah0, al0, bh0, bl0, 0, t);
    CP_COMMIT();

    const int NT = DIMN / BKT;   // 64
    for (int kt = 0; kt < NT; kt++) {
        const uint32_t stg = base + (uint32_t)(kt & 1) * STG_BYTES;
        if (kt + 1 < NT) {
            fill_stage(base + (uint32_t)((kt + 1) & 1) * STG_BYTES,
                       ah0, al0, bh0, bl0, (kt + 1) * BKT, t);
            CP_COMMIT();
            asm volatile("cp.async.wait_group 1;\n");
        } else {
            asm volatile("cp.async.wait_group 0;\n");
        }
        __syncthreads();

        const uint32_t As_h = stg;
        const uint32_t As_l = stg + ASTRIDE;
        const uint32_t Bs_h = stg + 2 * ASTRIDE;
        const uint32_t Bs_l = stg + 3 * ASTRIDE;

        #pragma unroll
        for (int ks = 0; ks < 2; ks++) {
            const uint32_t kb = (uint32_t)ks * 32;
            uint32_t Afh[4][4], Afl[4][4];
            #pragma unroll
            for (int mi = 0; mi < 4; mi++) {
                uint32_t ro = (uint32_t)(wm * 64 + mi * 16) + a_lrow;
                uint32_t off = ro * ROWB + kb + a_khalf;
                ldsm_x4(As_h + off, Afh[mi]);
                ldsm_x4(As_l + off, Afl[mi]);
            }
            #pragma unroll
            for (int ni = 0; ni < 4; ni++) {
                uint32_t ro = (uint32_t)(wn * 32 + ni * 8) + b_lrow;
                uint32_t off = ro * ROWB + kb + b_khalf;
                uint32_t Bfh[2], Bfl[2];
                ldsm_x2(Bs_h + off, Bfh);
                ldsm_x2(Bs_l + off, Bfl);
                #pragma unroll
                for (int mi = 0; mi < 4; mi++) {
                    mma_bf16(acc[mi][ni], Afh[mi], Bfh);
                    mma_bf16(acc[mi][ni], Afl[mi], Bfh);
                    mma_bf16(acc[mi][ni], Afh[mi], Bfl);
                }
            }
        }
        __syncthreads();
    }

    // epilogue: thread t: c0,c1 at (gr, 2tg), c2,c3 at (gr+8, 2tg)
    const int gr = lane >> 2, tg = lane & 3;
    #pragma unroll
    for (int mi = 0; mi < 4; mi++) {
        #pragma unroll
        for (int ni = 0; ni < 4; ni++) {
            const int m = bm + wm * 64 + mi * 16 + gr;
            const int n = bn + wn * 32 + ni * 8 + tg * 2;
            *(float2*)(C + (size_t)m * DIMN + n) =
                make_float2(acc[mi][ni][0], acc[mi][ni][1]);
            *(float2*)(C + (size_t)(m + 8) * DIMN + n) =
                make_float2(acc[mi][ni][2], acc[mi][ni][3]);
        }
    }
}

// ---------------------------------------------------------------------------
// RoPE on q and k, layout [B*S, DIM]. Adjacent-pair rotation.
// ---------------------------------------------------------------------------
__global__ void rope_kernel(float* __restrict__ q, float* __restrict__ k) {
    int idx = blockIdx.x * blockDim.x + threadIdx.x;   // pair index
    int pair = idx & (DIMN / 2 - 1);
    int row  = idx >> 10;
    int s    = row & (SS - 1);
    int dp   = pair & (HDD / 2 - 1);

    float inv = powf(10000.0f, -(float)dp * (1.0f / 64.0f));
    float ang = (float)s * inv;
    float sn, cs;
    sincosf(ang, &sn, &cs);

    size_t bse = (size_t)row * DIMN + 2 * pair;
    float2 qe = *(float2*)(q + bse);
    *(float2*)(q + bse) = make_float2(qe.x * cs - qe.y * sn, qe.x * sn + qe.y * cs);
    float2 ke = *(float2*)(k + bse);
    *(float2*)(k + bse) = make_float2(ke.x * cs - ke.y * sn, ke.x * sn + ke.y * cs);
}

// ---------------------------------------------------------------------------
// Flash attention, causal, BM=BN=64, HD=128, 256 threads (fp32).
// ---------------------------------------------------------------------------
#define FLASH_SMEM ((64*129*2 + 64*128 + 64*65) * 4)

__global__ __launch_bounds__(256, 1)
void flash_kernel(const float* __restrict__ Q, const float* __restrict__ K,
                  const float* __restrict__ V, float* __restrict__ O) {
    extern __shared__ float sm[];
    float* Qs = sm;                    // [64][129]
    float* Ks = sm + 64 * 129;         // [64][129]
    float* Vs = Ks + 64 * 129;         // [64][128]
    float* Ss = Vs + 64 * 128;         // [64][65]

    const int t  = threadIdx.x;
    const int qt = blockIdx.x, h = blockIdx.y, b = blockIdx.z;
    const int q0 = qt * 64;
    const float scale = 0.08838834764831845f;   // 1/sqrt(128)

    const float* Qp = Q + ((size_t)b * SS) * DIMN + h * HDD;
    const float* Kp = K + ((size_t)b * SS) * DIMN + h * HDD;
    const float* Vp = V + ((size_t)b * SS) * DIMN + h * HDD;

    for (int i = t; i < 64 * 32; i += 256) {
        int r = i >> 5, c = (i & 31) << 2;
        float4 v4 = *(const float4*)(Qp + (size_t)(q0 + r) * DIMN + c);
        float* dst = Qs + r * 129 + c;
        dst[0] = v4.x; dst[1] = v4.y; dst[2] = v4.z; dst[3] = v4.w;
    }

    const int tmq = t >> 4, tnq = t & 15;
    const int i0 = tmq * 4, j0 = tnq * 4;
    const int r = t >> 2, q4 = t & 3;

    float4 acc[8];
    #pragma unroll
    for (int jj = 0; jj < 8; jj++) acc[jj] = make_float4(0.f, 0.f, 0.f, 0.f);
    float mval = -CUDART_INF_F, lval = 0.f;

    for (int kt = 0; kt <= qt; kt++) {
        const int k0 = kt * 64;
        __syncthreads();
        for (int i = t; i < 64 * 32; i += 256) {
            int rr = i >> 5, c = (i & 31) << 2;
            float4 kv = *(const float4*)(Kp + (size_t)(k0 + rr) * DIMN + c);
            float* kd = Ks + rr * 129 + c;
            kd[0] = kv.x; kd[1] = kv.y; kd[2] = kv.z; kd[3] = kv.w;
            *(float4*)(Vs + rr * 128 + c) =
                *(const float4*)(Vp + (size_t)(k0 + rr) * DIMN + c);
        }
        __syncthreads();

        float cacc[4][4];
        #pragma unroll
        for (int x = 0; x < 4; x++)
            #pragma unroll
            for (int y = 0; y < 4; y++) cacc[x][y] = 0.f;
        #pragma unroll 4
        for (int d = 0; d < 128; d++) {
            float qr[4], kr[4];
            #pragma unroll
            for (int x = 0; x < 4; x++) qr[x] = Qs[(i0 + x) * 129 + d];
            #pragma unroll
            for (int y = 0; y < 4; y++) kr[y] = Ks[(j0 + y) * 129 + d];
            #pragma unroll
            for (int x = 0; x < 4; x++)
                #pragma unroll
                for (int y = 0; y < 4; y++) cacc[x][y] += qr[x] * kr[y];
        }
        #pragma unroll
        for (int x = 0; x < 4; x++) {
            int gi = q0 + i0 + x;
            #pragma unroll
            for (int y = 0; y < 4; y++) {
                int gj = k0 + j0 + y;
                float sv = cacc[x][y] * scale;
                if (gj > gi) sv = -CUDART_INF_F;
                Ss[(i0 + x) * 65 + j0 + y] = sv;
            }
        }
        __syncthreads();

        float* srow = Ss + r * 65;
        float mloc = -CUDART_INF_F;
        #pragma unroll
        for (int j = 0; j < 16; j++) mloc = fmaxf(mloc, srow[q4 * 16 + j]);
        mloc = fmaxf(mloc, __shfl_xor_sync(0xFFFFFFFFu, mloc, 1));
        mloc = fmaxf(mloc, __shfl_xor_sync(0xFFFFFFFFu, mloc, 2));
        float mnew = fmaxf(mval, mloc);
        float corr = __expf(mval - mnew);
        float lloc = 0.f;
        #pragma unroll
        for (int j = 0; j < 16; j++) {
            float p = __expf(srow[q4 * 16 + j] - mnew);
            srow[q4 * 16 + j] = p;
            lloc += p;
        }
        lloc += __shfl_xor_sync(0xFFFFFFFFu, lloc, 1);
        lloc += __shfl_xor_sync(0xFFFFFFFFu, lloc, 2);
        lval = lval * corr + lloc;
        mval = mnew;
        #pragma unroll
        for (int jj = 0; jj < 8; jj++) {
            acc[jj].x *= corr; acc[jj].y *= corr;
            acc[jj].z *= corr; acc[jj].w *= corr;
        }
        __syncwarp();

        for (int kk = 0; kk < 64; kk++) {
            float p = srow[kk];
            const float* vr = Vs + kk * 128 + q4 * 4;
            #pragma unroll
            for (int jj = 0; jj < 8; jj++) {
                float4 vv = *(const float4*)(vr + jj * 16);
                acc[jj].x += p * vv.x; acc[jj].y += p * vv.y;
                acc[jj].z += p * vv.z; acc[jj].w += p * vv.w;
            }
        }
    }

    float invl = 1.f / lval;
    float* orow = O + ((size_t)b * SS + q0 + r) * DIMN + h * HDD + q4 * 4;
    #pragma unroll
    for (int jj = 0; jj < 8; jj++) {
        float4 w = acc[jj];
        w.x *= invl; w.y *= invl; w.z *= invl; w.w *= invl;
        *(float4*)(orow + jj * 16) = w;
    }
}

// ---------------------------------------------------------------------------
extern "C" void kernel_launch(void* const* d_in, const int* in_sizes, int n_in,
                              void* d_out, int out_size) {
    const float* x  = (const float*)d_in[0];
    const float* Wq = (const float*)d_in[1];
    const float* Wk = (const float*)d_in[2];
    const float* Wv = (const float*)d_in[3];
    const float* Wo = (const float*)d_in[4];
    float* out = (float*)d_out;

    float *q, *k, *v, *att;
    cudaGetSymbolAddress((void**)&q, g_q);
    cudaGetSymbolAddress((void**)&k, g_k);
    cudaGetSymbolAddress((void**)&v, g_v);
    cudaGetSymbolAddress((void**)&att, g_att);
    __nv_bfloat16 *xh, *xl, *ath, *atl, *wth, *wtl;
    cudaGetSymbolAddress((void**)&xh,  g_xh);
    cudaGetSymbolAddress((void**)&xl,  g_xl);
    cudaGetSymbolAddress((void**)&ath, g_ath);
    cudaGetSymbolAddress((void**)&atl, g_atl);
    cudaGetSymbolAddress((void**)&wth, g_wth);
    cudaGetSymbolAddress((void**)&wtl, g_wtl);
    const size_t WSZ = (size_t)DIMN * DIMN;

    cudaFuncSetAttribute(hgemm3,
                         cudaFuncAttributeMaxDynamicSharedMemorySize, GSMEM);
    cudaFuncSetAttribute(flash_kernel,
                         cudaFuncAttributeMaxDynamicSharedMemorySize, FLASH_SMEM);

    // prep: splits + weight transposes
    split_rows<<<(MTOT * DIMN) / 1024, 256>>>(x, xh, xl);
    dim3 tg(DIMN / 32, DIMN / 32), tb(32, 8);
    split_transpose<<<tg, tb>>>(Wq, wth + 0 * WSZ, wtl + 0 * WSZ);
    split_transpose<<<tg, tb>>>(Wk, wth + 1 * WSZ, wtl + 1 * WSZ);
    split_transpose<<<tg, tb>>>(Wv, wth + 2 * WSZ, wtl + 2 * WSZ);
    split_transpose<<<tg, tb>>>(Wo, wth + 3 * WSZ, wtl + 3 * WSZ);

    // projections on mma.sync bf16 (3-term split)
    dim3 gg(DIMN / 128, MTOT / 128);   // (16, 32)
    hgemm3<<<gg, 256, GSMEM>>>(xh, xl, wth + 0 * WSZ, wtl + 0 * WSZ, q);
    hgemm3<<<gg, 256, GSMEM>>>(xh, xl, wth + 1 * WSZ, wtl + 1 * WSZ, k);
    hgemm3<<<gg, 256, GSMEM>>>(xh, xl, wth + 2 * WSZ, wtl + 2 * WSZ, v);

    rope_kernel<<<(MTOT * (DIMN / 2)) / 256, 256>>>(q, k);

    flash_kernel<<<dim3(SS / 64, HH, BB), 256, FLASH_SMEM>>>(q, k, v, att);

    // output projection
    split_rows<<<(MTOT * DIMN) / 1024, 256>>>(att, ath, atl);
    hgemm3<<<gg, 256, GSMEM>>>(ath, atl, wth + 3 * WSZ, wtl + 3 * WSZ, out);
}